// round 3
// baseline (speedup 1.0000x reference)
#include <cuda_runtime.h>
#include <cuda_bf16.h>
#include <cstdint>

#define Bsz 512
#define Cc  271
#define Tt  281
#define Hh  128
#define NCLS 1854
#define BT  (Bsz*Tt)      /* 143872 */
#define G4  512

typedef unsigned long long u64;

union F4 { float4 v; float f[4]; u64 d[2]; };

__device__ __forceinline__ u64 ffma2(u64 a, u64 b, u64 c){
    u64 d; asm("fma.rn.f32x2 %0, %1, %2, %3;" : "=l"(d) : "l"(a), "l"(b), "l"(c)); return d;
}
__device__ __forceinline__ float2 unpack2(u64 d){
    float lo, hi; asm("mov.b64 {%0, %1}, %2;" : "=f"(lo), "=f"(hi) : "l"(d));
    return make_float2(lo, hi);
}
__device__ __forceinline__ float sigf(float x){ return __fdividef(1.f, 1.f + __expf(-x)); }
__device__ __forceinline__ float tanh_(float x){ return 1.f - __fdividef(2.f, __expf(2.f*x) + 1.f); }

// ------------- device scratch -------------
__device__ float g_xT [(size_t)BT*Cc];
__device__ float g_xwF[(size_t)BT*G4];
__device__ float g_xwB[(size_t)BT*G4];
__device__ float g_h0 [(size_t)BT*2*Hh];
__device__ float g_h1 [(size_t)BT*2*Hh];
__device__ float g_wT [4*Hh*G4];          // 4x [128][512] gate-interleaved W_hh^T
__device__ float g_wih0[2*G4*Cc];         // reordered w_ih layer0
__device__ float g_wih1[2*G4*2*Hh];       // reordered w_ih layer1
__device__ float g_bsum[4*G4];
__device__ float g_att[Bsz*2*Hh];

__device__ __forceinline__ int oldrow(int n){ return (n&3)*128 + (n>>2); }

// ------------- prep kernels -------------
__global__ void reorder_wih(const float* __restrict__ src, float* __restrict__ dst, int K){
    int i = blockIdx.x*256 + threadIdx.x;
    if (i >= G4*K) return;
    int n = i / K, k = i % K;
    dst[i] = src[oldrow(n)*K + k];
}
__global__ void reorder_whh(const float* __restrict__ src, float* __restrict__ dst){
    int i = blockIdx.x*256 + threadIdx.x;
    if (i >= Hh*G4) return;
    int k = i >> 9, n = i & 511;
    dst[i] = src[oldrow(n)*Hh + k];
}
__global__ void fold_b(const float* __restrict__ bi, const float* __restrict__ bh, float* __restrict__ dst){
    int n = blockIdx.x*256 + threadIdx.x;
    if (n >= G4) return;
    int o = oldrow(n);
    dst[n] = bi[o] + bh[o];
}

// ------------- transpose X[B,C,T] -> xT[B,T,C] -------------
__global__ void transposeX(const float* __restrict__ X, float* __restrict__ xT){
    __shared__ float tile[32][33];
    int b = blockIdx.z;
    int t0 = blockIdx.x*32, c0 = blockIdx.y*32;
    int tx = threadIdx.x, ty = threadIdx.y;
    const float* Xb = X + (size_t)b*Cc*Tt;
    float* xTb = xT + (size_t)b*Tt*Cc;
    #pragma unroll
    for (int i=0;i<32;i+=8){
        int c = c0+ty+i, t = t0+tx;
        if (c<Cc && t<Tt) tile[ty+i][tx] = Xb[(size_t)c*Tt + t];
    }
    __syncthreads();
    #pragma unroll
    for (int i=0;i<32;i+=8){
        int t = t0+ty+i, c = c0+tx;
        if (t<Tt && c<Cc) xTb[(size_t)t*Cc + c] = tile[tx][ty+i];
    }
}

// ------------- fp32 GEMM, f32x2 core. C = act(A@B(+bias)) -------------
// transB=1: B is [N,K] (C = A@B^T). transB=0: B is [K,N].
__global__ __launch_bounds__(256,2)
void gemm128(const float* __restrict__ A, const float* __restrict__ B,
             const float* __restrict__ bias, float* __restrict__ C,
             int M, int N, int K, int transB, int act)
{
    __shared__ float As2[16][264];   // duplicated pairs: As2[kk][2r]=As2[kk][2r+1]
    __shared__ float Bs[16][132];
    int row0 = blockIdx.y*128, col0 = blockIdx.x*128;
    int tid = threadIdx.x;
    int tm = tid >> 4, tn = tid & 15;
    u64 acc[8][4];
    #pragma unroll
    for (int i=0;i<8;i++)
        #pragma unroll
        for (int j=0;j<4;j++) acc[i][j] = 0ull;

    for (int k0=0;k0<K;k0+=16){
        #pragma unroll
        for (int i=0;i<8;i++){
            int idx = tid + i*256;
            int r = idx >> 4, kk = idx & 15;
            int gr = row0+r, gk = k0+kk;
            float v = (gr<M && gk<K) ? A[(size_t)gr*K + gk] : 0.f;
            *(float2*)&As2[kk][2*r] = make_float2(v, v);
        }
        if (transB){
            #pragma unroll
            for (int i=0;i<8;i++){
                int idx = tid + i*256;
                int nn = idx >> 4, kk = idx & 15;
                int gk = k0+kk, gn = col0+nn;
                Bs[kk][nn] = (gk<K && gn<N) ? B[(size_t)gn*K+gk] : 0.f;
            }
        } else {
            #pragma unroll
            for (int i=0;i<8;i++){
                int idx = tid + i*256;
                int nn = idx & 127, kk = idx >> 7;
                int gk = k0+kk, gn = col0+nn;
                Bs[kk][nn] = (gk<K && gn<N) ? B[(size_t)gk*N+gn] : 0.f;
            }
        }
        __syncthreads();
        #pragma unroll
        for (int kk=0;kk<16;kk++){
            F4 b0, b1, a0, a1, a2, a3;
            b0.v = *(const float4*)&Bs[kk][tn*8];
            b1.v = *(const float4*)&Bs[kk][tn*8+4];
            a0.v = *(const float4*)&As2[kk][tm*16];
            a1.v = *(const float4*)&As2[kk][tm*16+4];
            a2.v = *(const float4*)&As2[kk][tm*16+8];
            a3.v = *(const float4*)&As2[kk][tm*16+12];
            u64 bd[4] = { b0.d[0], b0.d[1], b1.d[0], b1.d[1] };
            u64 ad[8] = { a0.d[0], a0.d[1], a1.d[0], a1.d[1],
                          a2.d[0], a2.d[1], a3.d[0], a3.d[1] };
            #pragma unroll
            for (int i=0;i<8;i++)
                #pragma unroll
                for (int j=0;j<4;j++)
                    acc[i][j] = ffma2(ad[i], bd[j], acc[i][j]);
        }
        __syncthreads();
    }
    #pragma unroll
    for (int i=0;i<8;i++){
        int gr = row0 + tm*8 + i;
        if (gr >= M) continue;
        #pragma unroll
        for (int j=0;j<4;j++){
            float2 v = unpack2(acc[i][j]);
            int gn = col0 + tn*8 + j*2;
            if (gn < N){
                float x = v.x + (bias ? bias[gn] : 0.f);
                if (act) x = tanh_(x);
                C[(size_t)gr*N + gn] = x;
            }
            if (gn+1 < N){
                float y = v.y + (bias ? bias[gn+1] : 0.f);
                if (act) y = tanh_(y);
                C[(size_t)gr*N + gn+1] = y;
            }
        }
    }
}

// ------------- LSTM scan: one layer, both directions concurrently -------------
// 128 CTAs: blockIdx>>6 = dir, (blockIdx&63)*8 = batch base. 256 threads.
// thread t: hcol h = t&127, rowgroup rg = t>>7 (rows 4rg..4rg+3).
// gate-interleaved: wT[k][4h..4h+3] = (i,f,g,o) weights, xw likewise.
#define HS 20
#define SCAN_SMEM ((64*G4 + 128*HS)*4)

__global__ __launch_bounds__(256,1)
void scan_kernel(const float* __restrict__ xwFp, const float* __restrict__ xwBp,
                 const float* __restrict__ wTF, const float* __restrict__ wTB,
                 float* __restrict__ hout)
{
    extern __shared__ float sm[];
    float* Ws = sm;                  // [64][512]
    float* hs = sm + 64*G4;          // [128][HS] dup pairs (h of 8 rows)
    int tid = threadIdx.x;
    int dir = blockIdx.x >> 6;
    int grp = blockIdx.x & 63;
    int b0 = grp*8;
    const float* xw = dir ? xwBp : xwFp;
    const float* wD = dir ? wTB : wTF;
    int hOff = dir*128;
    int h  = tid & 127;
    int rg = tid >> 7;

    for (int i=tid;i<64*G4;i+=256) Ws[i] = wD[i];
    for (int i=tid;i<128*HS;i+=256) hs[i] = 0.f;
    float cst[4] = {0.f,0.f,0.f,0.f};
    __syncthreads();

    for (int s=0;s<Tt;s++){
        int t = dir ? (Tt-1-s) : s;
        F4 xv[4];
        #pragma unroll
        for (int r=0;r<4;r++)
            xv[r].v = *(const float4*)&xw[((size_t)(b0+4*rg+r)*Tt + t)*G4 + 4*h];

        u64 aIF[4] = {0,0,0,0}, aGO[4] = {0,0,0,0};
        // SMEM half of W
        #pragma unroll 8
        for (int k=0;k<64;k++){
            F4 w;  w.v  = *(const float4*)&Ws[k*G4 + 4*h];
            F4 p0; p0.v = *(const float4*)&hs[k*HS + 8*rg];
            F4 p1; p1.v = *(const float4*)&hs[k*HS + 8*rg + 4];
            aIF[0]=ffma2(p0.d[0], w.d[0], aIF[0]); aGO[0]=ffma2(p0.d[0], w.d[1], aGO[0]);
            aIF[1]=ffma2(p0.d[1], w.d[0], aIF[1]); aGO[1]=ffma2(p0.d[1], w.d[1], aGO[1]);
            aIF[2]=ffma2(p1.d[0], w.d[0], aIF[2]); aGO[2]=ffma2(p1.d[0], w.d[1], aGO[2]);
            aIF[3]=ffma2(p1.d[1], w.d[0], aIF[3]); aGO[3]=ffma2(p1.d[1], w.d[1], aGO[3]);
        }
        // global (L2) half of W
        for (int kb=64;kb<128;kb+=8){
            F4 w[8];
            #pragma unroll
            for (int j=0;j<8;j++) w[j].v = *(const float4*)&wD[(size_t)(kb+j)*G4 + 4*h];
            #pragma unroll
            for (int j=0;j<8;j++){
                int k = kb+j;
                F4 p0; p0.v = *(const float4*)&hs[k*HS + 8*rg];
                F4 p1; p1.v = *(const float4*)&hs[k*HS + 8*rg + 4];
                aIF[0]=ffma2(p0.d[0], w[j].d[0], aIF[0]); aGO[0]=ffma2(p0.d[0], w[j].d[1], aGO[0]);
                aIF[1]=ffma2(p0.d[1], w[j].d[0], aIF[1]); aGO[1]=ffma2(p0.d[1], w[j].d[1], aGO[1]);
                aIF[2]=ffma2(p1.d[0], w[j].d[0], aIF[2]); aGO[2]=ffma2(p1.d[0], w[j].d[1], aGO[2]);
                aIF[3]=ffma2(p1.d[1], w[j].d[0], aIF[3]); aGO[3]=ffma2(p1.d[1], w[j].d[1], aGO[3]);
            }
        }
        __syncthreads();   // everyone done reading hs
        float hnew[4];
        #pragma unroll
        for (int r=0;r<4;r++){
            float2 v1 = unpack2(aIF[r]);
            float2 v2 = unpack2(aGO[r]);
            float gi = v1.x + xv[r].f[0];
            float gf = v1.y + xv[r].f[1];
            float gg = v2.x + xv[r].f[2];
            float go = v2.y + xv[r].f[3];
            float cc = sigf(gf)*cst[r] + sigf(gi)*tanh_(gg);
            cst[r] = cc;
            hnew[r] = sigf(go)*tanh_(cc);
        }
        #pragma unroll
        for (int r=0;r<4;r++){
            *(float2*)&hs[h*HS + 2*(4*rg+r)] = make_float2(hnew[r], hnew[r]);
            hout[((size_t)(b0+4*rg+r)*Tt + t)*256 + hOff + h] = hnew[r];
        }
        __syncthreads();
    }
}

// ------------- attention: scores + softmax + weighted sum -------------
__global__ __launch_bounds__(256,1)
void att_kernel(const float* __restrict__ u, const float* __restrict__ h1,
                const float* __restrict__ v, float* __restrict__ att)
{
    __shared__ float sa[Tt];
    __shared__ float red[256];
    int b = blockIdx.x, tid = threadIdx.x;
    for (int t = tid; t < Tt; t += 256){
        const float* ur = u + ((size_t)b*Tt + t)*256;
        float s = 0.f;
        #pragma unroll 8
        for (int k=0;k<256;k++) s += ur[k]*v[k];
        sa[t] = s;
    }
    __syncthreads();
    float m = -3.4e38f;
    for (int t=tid;t<Tt;t+=256) m = fmaxf(m, sa[t]);
    red[tid] = m; __syncthreads();
    for (int off=128; off>0; off>>=1){ if (tid<off) red[tid]=fmaxf(red[tid],red[tid+off]); __syncthreads(); }
    float mx = red[0]; __syncthreads();
    float sum = 0.f;
    for (int t=tid;t<Tt;t+=256){ float e = __expf(sa[t]-mx); sa[t]=e; sum+=e; }
    red[tid] = sum; __syncthreads();
    for (int off=128; off>0; off>>=1){ if (tid<off) red[tid]+=red[tid+off]; __syncthreads(); }
    float inv = __fdividef(1.f, red[0]);
    __syncthreads();
    float acc = 0.f;
    const float* hb = h1 + (size_t)b*Tt*256 + tid;
    #pragma unroll 4
    for (int t=0;t<Tt;t++) acc += hb[(size_t)t*256] * sa[t];
    att[b*256 + tid] = acc * inv;
}

// ------------- launch -------------
extern "C" void kernel_launch(void* const* d_in, const int* in_sizes, int n_in,
                              void* d_out, int out_size)
{
    const float* X      = (const float*)d_in[0];
    const float* wih0f  = (const float*)d_in[1];
    const float* whh0f  = (const float*)d_in[2];
    const float* bih0f  = (const float*)d_in[3];
    const float* bhh0f  = (const float*)d_in[4];
    const float* wih0b  = (const float*)d_in[5];
    const float* whh0b  = (const float*)d_in[6];
    const float* bih0b  = (const float*)d_in[7];
    const float* bhh0b  = (const float*)d_in[8];
    const float* wih1f  = (const float*)d_in[9];
    const float* whh1f  = (const float*)d_in[10];
    const float* bih1f  = (const float*)d_in[11];
    const float* bhh1f  = (const float*)d_in[12];
    const float* wih1b  = (const float*)d_in[13];
    const float* whh1b  = (const float*)d_in[14];
    const float* bih1b  = (const float*)d_in[15];
    const float* bhh1b  = (const float*)d_in[16];
    const float* attW   = (const float*)d_in[17];
    const float* attV   = (const float*)d_in[18];
    const float* headW  = (const float*)d_in[19];
    const float* headB  = (const float*)d_in[20];
    float* out = (float*)d_out;

    cudaFuncSetAttribute(scan_kernel, cudaFuncAttributeMaxDynamicSharedMemorySize, SCAN_SMEM);

    float *xT, *xwF, *xwB, *h0, *h1, *wT, *wi0, *wi1, *bsum, *att;
    cudaGetSymbolAddress((void**)&xT,  g_xT);
    cudaGetSymbolAddress((void**)&xwF, g_xwF);
    cudaGetSymbolAddress((void**)&xwB, g_xwB);
    cudaGetSymbolAddress((void**)&h0,  g_h0);
    cudaGetSymbolAddress((void**)&h1,  g_h1);
    cudaGetSymbolAddress((void**)&wT,  g_wT);
    cudaGetSymbolAddress((void**)&wi0, g_wih0);
    cudaGetSymbolAddress((void**)&wi1, g_wih1);
    cudaGetSymbolAddress((void**)&bsum,g_bsum);
    cudaGetSymbolAddress((void**)&att, g_att);

    // prep: reorder weights into gate-interleaved layouts, fold biases
    reorder_wih<<<(G4*Cc+255)/256, 256>>>(wih0f, wi0,            Cc);
    reorder_wih<<<(G4*Cc+255)/256, 256>>>(wih0b, wi0 + G4*Cc,    Cc);
    reorder_wih<<<(G4*256+255)/256,256>>>(wih1f, wi1,            256);
    reorder_wih<<<(G4*256+255)/256,256>>>(wih1b, wi1 + G4*256,   256);
    reorder_whh<<<(Hh*G4+255)/256, 256>>>(whh0f, wT + 0*Hh*G4);
    reorder_whh<<<(Hh*G4+255)/256, 256>>>(whh0b, wT + 1*Hh*G4);
    reorder_whh<<<(Hh*G4+255)/256, 256>>>(whh1f, wT + 2*Hh*G4);
    reorder_whh<<<(Hh*G4+255)/256, 256>>>(whh1b, wT + 3*Hh*G4);
    fold_b<<<2,256>>>(bih0f, bhh0f, bsum + 0*G4);
    fold_b<<<2,256>>>(bih0b, bhh0b, bsum + 1*G4);
    fold_b<<<2,256>>>(bih1f, bhh1f, bsum + 2*G4);
    fold_b<<<2,256>>>(bih1b, bhh1b, bsum + 3*G4);

    transposeX<<<dim3((Tt+31)/32,(Cc+31)/32,Bsz), dim3(32,8)>>>(X, xT);

    dim3 gXW(4, (BT+127)/128);
    // layer 0 input projections
    gemm128<<<gXW,256>>>(xT, wi0,         bsum + 0*G4, xwF, BT, G4, Cc, 1, 0);
    gemm128<<<gXW,256>>>(xT, wi0 + G4*Cc, bsum + 1*G4, xwB, BT, G4, Cc, 1, 0);
    // layer 0 scan
    scan_kernel<<<128,256,SCAN_SMEM>>>(xwF, xwB, wT + 0*Hh*G4, wT + 1*Hh*G4, h0);
    // layer 1 input projections
    gemm128<<<gXW,256>>>(h0, wi1,          bsum + 2*G4, xwF, BT, G4, 256, 1, 0);
    gemm128<<<gXW,256>>>(h0, wi1 + G4*256, bsum + 3*G4, xwB, BT, G4, 256, 1, 0);
    // layer 1 scan
    scan_kernel<<<128,256,SCAN_SMEM>>>(xwF, xwB, wT + 2*Hh*G4, wT + 3*Hh*G4, h1);
    // attention u = tanh(h1 @ att_W)  (reuse xwF as u buffer)
    gemm128<<<dim3(2,(BT+127)/128),256>>>(h1, attW, (const float*)0, xwF, BT, 256, 256, 0, 1);
    // scores + softmax + weighted sum
    att_kernel<<<Bsz,256>>>(xwF, h1, attV, att);
    // head
    gemm128<<<dim3((NCLS+127)/128,(Bsz+127)/128),256>>>(att, headW, headB, out, Bsz, NCLS, 256, 1, 0);
}

// round 4
// speedup vs baseline: 1.4515x; 1.4515x over previous
#include <cuda_runtime.h>
#include <cuda_bf16.h>
#include <cstdint>

#define Bsz 512
#define Cc  271
#define Tt  281
#define Hh  128
#define NCLS 1854
#define BT  (Bsz*Tt)      /* 143872 */
#define G4  512
#define KP0 272           /* padded K for layer0 */

typedef unsigned long long u64;
typedef unsigned int u32;

union F4 { float4 v; float f[4]; u64 d[2]; };

__device__ __forceinline__ u64 ffma2(u64 a, u64 b, u64 c){
    u64 d; asm("fma.rn.f32x2 %0, %1, %2, %3;" : "=l"(d) : "l"(a), "l"(b), "l"(c)); return d;
}
__device__ __forceinline__ float2 unpack2(u64 d){
    float lo, hi; asm("mov.b64 {%0, %1}, %2;" : "=f"(lo), "=f"(hi) : "l"(d));
    return make_float2(lo, hi);
}
__device__ __forceinline__ float sigf(float x){ return __fdividef(1.f, 1.f + __expf(-x)); }
__device__ __forceinline__ float tanh_(float x){ return 1.f - __fdividef(2.f, __expf(2.f*x) + 1.f); }

// ------------- device scratch -------------
__device__ float g_xT [(size_t)BT*Cc];
__device__ float g_xwF[(size_t)BT*G4];
__device__ float g_xwB[(size_t)BT*G4];
__device__ float g_h0 [(size_t)BT*2*Hh];
__device__ float g_h1 [(size_t)BT*2*Hh];
__device__ float g_wT [4*Hh*G4];          // 4x [128][512] gate-interleaved W_hh^T
__device__ float g_wih0[2*G4*Cc];         // reordered w_ih layer0 (fp32)
__device__ float g_wih1[2*G4*2*Hh];       // reordered w_ih layer1 (fp32)
__device__ float g_bsum[4*G4];
__device__ float g_att[Bsz*2*Hh];
// bf16 split buffers
__device__ __nv_bfloat16 g_ahi[(size_t)BT*KP0];
__device__ __nv_bfloat16 g_alo[(size_t)BT*KP0];
#define WOFF0F 0
#define WOFF0B (512*KP0)
#define WOFF1F (2*512*KP0)
#define WOFF1B (2*512*KP0 + 512*256)
#define WOFFATT (2*512*KP0 + 2*512*256)
#define WTOT (WOFFATT + 256*256)
__device__ __nv_bfloat16 g_whi[WTOT];
__device__ __nv_bfloat16 g_wlo[WTOT];

__device__ __forceinline__ int oldrow(int n){ return (n&3)*128 + (n>>2); }

// ------------- prep kernels -------------
__global__ void reorder_wih(const float* __restrict__ src, float* __restrict__ dst, int K){
    int i = blockIdx.x*256 + threadIdx.x;
    if (i >= G4*K) return;
    int n = i / K, k = i % K;
    dst[i] = src[oldrow(n)*K + k];
}
__global__ void reorder_whh(const float* __restrict__ src, float* __restrict__ dst){
    int i = blockIdx.x*256 + threadIdx.x;
    if (i >= Hh*G4) return;
    int k = i >> 9, n = i & 511;
    dst[i] = src[oldrow(n)*Hh + k];
}
__global__ void fold_b(const float* __restrict__ bi, const float* __restrict__ bh, float* __restrict__ dst){
    int n = blockIdx.x*256 + threadIdx.x;
    if (n >= G4) return;
    int o = oldrow(n);
    dst[n] = bi[o] + bh[o];
}

// ------------- fp32 -> bf16 hi/lo split (with K padding) -------------
__global__ void conv_split(const float* __restrict__ src, __nv_bfloat16* __restrict__ hi,
                           __nv_bfloat16* __restrict__ lo, size_t total, int Ks, int Kp){
    size_t i = (size_t)blockIdx.x*256 + threadIdx.x;
    if (i >= total) return;
    size_t r = i / Kp; int k = (int)(i - r*Kp);
    float v = (k < Ks) ? src[r*Ks + k] : 0.f;
    __nv_bfloat16 h = __float2bfloat16(v);
    hi[i] = h;
    lo[i] = __float2bfloat16(v - __bfloat162float(h));
}
// transposed: src is [K][N]; dst row n holds src[:,n]
__global__ void conv_splitT(const float* __restrict__ src, __nv_bfloat16* __restrict__ hi,
                            __nv_bfloat16* __restrict__ lo, int N, int Ks, int Kp){
    int i = blockIdx.x*256 + threadIdx.x;
    if (i >= N*Kp) return;
    int n = i / Kp, k = i % Kp;
    float v = (k < Ks) ? src[(size_t)k*N + n] : 0.f;
    __nv_bfloat16 h = __float2bfloat16(v);
    hi[i] = h;
    lo[i] = __float2bfloat16(v - __bfloat162float(h));
}

// ------------- transpose X[B,C,T] -> xT[B,T,C] -------------
__global__ void transposeX(const float* __restrict__ X, float* __restrict__ xT){
    __shared__ float tile[32][33];
    int b = blockIdx.z;
    int t0 = blockIdx.x*32, c0 = blockIdx.y*32;
    int tx = threadIdx.x, ty = threadIdx.y;
    const float* Xb = X + (size_t)b*Cc*Tt;
    float* xTb = xT + (size_t)b*Tt*Cc;
    #pragma unroll
    for (int i=0;i<32;i+=8){
        int c = c0+ty+i, t = t0+tx;
        if (c<Cc && t<Tt) tile[ty+i][tx] = Xb[(size_t)c*Tt + t];
    }
    __syncthreads();
    #pragma unroll
    for (int i=0;i<32;i+=8){
        int t = t0+ty+i, c = c0+tx;
        if (t<Tt && c<Cc) xTb[(size_t)t*Cc + c] = tile[tx][ty+i];
    }
}

// ------------- tensor-core GEMM with split-bf16 (3 passes = fp32 accuracy) -------
// C[M,N] = act(A[M,K] @ W[N,K]^T + bias).  M,N multiples of 128. Kp multiple of 16.
#define SST 24   /* smem row stride in halves */
__device__ __forceinline__ u32 smaddr(const void* p){ return (u32)__cvta_generic_to_shared(p); }
__device__ __forceinline__ void cpasync16(u32 s, const void* g){
    asm volatile("cp.async.cg.shared.global [%0], [%1], 16;" :: "r"(s), "l"(g));
}
__device__ __forceinline__ void ldsm4(u32* r, u32 a){
    asm volatile("ldmatrix.sync.aligned.m8n8.x4.shared.b16 {%0,%1,%2,%3}, [%4];"
        : "=r"(r[0]),"=r"(r[1]),"=r"(r[2]),"=r"(r[3]) : "r"(a));
}
__device__ __forceinline__ void mma16816(float* d, const u32* a, u32 b0, u32 b1){
    asm volatile("mma.sync.aligned.m16n8k16.row.col.f32.bf16.bf16.f32 "
        "{%0,%1,%2,%3}, {%4,%5,%6,%7}, {%8,%9}, {%0,%1,%2,%3};"
        : "+f"(d[0]),"+f"(d[1]),"+f"(d[2]),"+f"(d[3])
        : "r"(a[0]),"r"(a[1]),"r"(a[2]),"r"(a[3]), "r"(b0),"r"(b1));
}

__global__ __launch_bounds__(256,1)
void mma_gemm(const __nv_bfloat16* __restrict__ Ahi, const __nv_bfloat16* __restrict__ Alo,
              const __nv_bfloat16* __restrict__ Whi, const __nv_bfloat16* __restrict__ Wlo,
              const float* __restrict__ bias, float* __restrict__ C,
              int M, int N, int Kp, int act)
{
    __shared__ __align__(16) __nv_bfloat16 sm[2][4][128*SST];
    int tid = threadIdx.x;
    int wid = tid>>5, lane = tid&31;
    int m0 = blockIdx.y*128, n0 = blockIdx.x*128;
    int wm = (wid>>2)*64, wn = (wid&3)*32;

    float acc[4][4][4];
    #pragma unroll
    for (int i=0;i<4;i++)
      #pragma unroll
      for (int j=0;j<4;j++)
        #pragma unroll
        for (int q=0;q<4;q++) acc[i][j][q] = 0.f;

    const __nv_bfloat16* gsrc[4];
    gsrc[0] = Ahi + (size_t)m0*Kp;
    gsrc[1] = Alo + (size_t)m0*Kp;
    gsrc[2] = Whi + (size_t)n0*Kp;
    gsrc[3] = Wlo + (size_t)n0*Kp;

    int row = tid>>1, half = tid&1;
    int NC = Kp >> 4;

    // prologue load chunk 0 -> stage 0
    {
        int k0 = 0;
        #pragma unroll
        for (int t=0;t<4;t++){
            const __nv_bfloat16* g = gsrc[t] + (size_t)row*Kp + k0 + half*8;
            cpasync16(smaddr(&sm[0][t][row*SST + half*8]), g);
        }
        asm volatile("cp.async.commit_group;" ::: "memory");
    }

    // ldmatrix address components
    int ar = lane & 15;                       // A: row within 16-group
    int ac = (lane >> 4) * 8;                 // A: k offset (0 or 8)
    int brn = (lane & 7) + ((lane & 16) ? 8 : 0);  // W: n within 16-group
    int bc  = (lane & 8) ? 8 : 0;                  // W: k offset

    for (int c=0;c<NC;c++){
        if (c+1 < NC){
            int k0 = (c+1)*16, s = (c+1)&1;
            #pragma unroll
            for (int t=0;t<4;t++){
                const __nv_bfloat16* g = gsrc[t] + (size_t)row*Kp + k0 + half*8;
                cpasync16(smaddr(&sm[s][t][row*SST + half*8]), g);
            }
            asm volatile("cp.async.commit_group;" ::: "memory");
            asm volatile("cp.async.wait_group 1;" ::: "memory");
        } else {
            asm volatile("cp.async.wait_group 0;" ::: "memory");
        }
        __syncthreads();
        int s = c & 1;
        const __nv_bfloat16* tA_hi = sm[s][0];
        const __nv_bfloat16* tA_lo = sm[s][1];
        const __nv_bfloat16* tW_hi = sm[s][2];
        const __nv_bfloat16* tW_lo = sm[s][3];

        u32 Af[4][4], Whf[2][4], Wlf[2][4];
        #pragma unroll
        for (int mi=0;mi<4;mi++)
            ldsm4(Af[mi], smaddr(&tA_hi[(wm + mi*16 + ar)*SST + ac]));
        #pragma unroll
        for (int g=0;g<2;g++)
            ldsm4(Whf[g], smaddr(&tW_hi[(wn + g*16 + brn)*SST + bc]));
        // pass 1: Ahi * Whi
        #pragma unroll
        for (int mi=0;mi<4;mi++)
            #pragma unroll
            for (int ni=0;ni<4;ni++)
                mma16816(acc[mi][ni], Af[mi], Whf[ni>>1][(ni&1)*2], Whf[ni>>1][(ni&1)*2+1]);
        // pass 2: Ahi * Wlo
        #pragma unroll
        for (int g=0;g<2;g++)
            ldsm4(Wlf[g], smaddr(&tW_lo[(wn + g*16 + brn)*SST + bc]));
        #pragma unroll
        for (int mi=0;mi<4;mi++)
            #pragma unroll
            for (int ni=0;ni<4;ni++)
                mma16816(acc[mi][ni], Af[mi], Wlf[ni>>1][(ni&1)*2], Wlf[ni>>1][(ni&1)*2+1]);
        // pass 3: Alo * Whi
        #pragma unroll
        for (int mi=0;mi<4;mi++)
            ldsm4(Af[mi], smaddr(&tA_lo[(wm + mi*16 + ar)*SST + ac]));
        #pragma unroll
        for (int mi=0;mi<4;mi++)
            #pragma unroll
            for (int ni=0;ni<4;ni++)
                mma16816(acc[mi][ni], Af[mi], Whf[ni>>1][(ni&1)*2], Whf[ni>>1][(ni&1)*2+1]);
        __syncthreads();
    }

    // epilogue
    int er = lane>>2, ec = (lane&3)*2;
    #pragma unroll
    for (int mi=0;mi<4;mi++){
        #pragma unroll
        for (int ni=0;ni<4;ni++){
            int gm = m0 + wm + mi*16 + er;
            int gn = n0 + wn + ni*8 + ec;
            float b0 = bias ? bias[gn]   : 0.f;
            float b1 = bias ? bias[gn+1] : 0.f;
            float v0 = acc[mi][ni][0] + b0;
            float v1 = acc[mi][ni][1] + b1;
            float v2 = acc[mi][ni][2] + b0;
            float v3 = acc[mi][ni][3] + b1;
            if (act){ v0 = tanh_(v0); v1 = tanh_(v1); v2 = tanh_(v2); v3 = tanh_(v3); }
            *(float2*)&C[(size_t)gm*N + gn]     = make_float2(v0, v1);
            *(float2*)&C[(size_t)(gm+8)*N + gn] = make_float2(v2, v3);
        }
    }
}

// ------------- fp32 GEMM (head only) -------------
__global__ __launch_bounds__(256,2)
void gemm128(const float* __restrict__ A, const float* __restrict__ B,
             const float* __restrict__ bias, float* __restrict__ C,
             int M, int N, int K, int transB, int act)
{
    __shared__ float As2[16][264];
    __shared__ float Bs[16][132];
    int row0 = blockIdx.y*128, col0 = blockIdx.x*128;
    int tid = threadIdx.x;
    int tm = tid >> 4, tn = tid & 15;
    u64 acc[8][4];
    #pragma unroll
    for (int i=0;i<8;i++)
        #pragma unroll
        for (int j=0;j<4;j++) acc[i][j] = 0ull;

    for (int k0=0;k0<K;k0+=16){
        #pragma unroll
        for (int i=0;i<8;i++){
            int idx = tid + i*256;
            int r = idx >> 4, kk = idx & 15;
            int gr = row0+r, gk = k0+kk;
            float v = (gr<M && gk<K) ? A[(size_t)gr*K + gk] : 0.f;
            *(float2*)&As2[kk][2*r] = make_float2(v, v);
        }
        if (transB){
            #pragma unroll
            for (int i=0;i<8;i++){
                int idx = tid + i*256;
                int nn = idx >> 4, kk = idx & 15;
                int gk = k0+kk, gn = col0+nn;
                Bs[kk][nn] = (gk<K && gn<N) ? B[(size_t)gn*K+gk] : 0.f;
            }
        } else {
            #pragma unroll
            for (int i=0;i<8;i++){
                int idx = tid + i*256;
                int nn = idx & 127, kk = idx >> 7;
                int gk = k0+kk, gn = col0+nn;
                Bs[kk][nn] = (gk<K && gn<N) ? B[(size_t)gk*N+gn] : 0.f;
            }
        }
        __syncthreads();
        #pragma unroll
        for (int kk=0;kk<16;kk++){
            F4 b0, b1, a0, a1, a2, a3;
            b0.v = *(const float4*)&Bs[kk][tn*8];
            b1.v = *(const float4*)&Bs[kk][tn*8+4];
            a0.v = *(const float4*)&As2[kk][tm*16];
            a1.v = *(const float4*)&As2[kk][tm*16+4];
            a2.v = *(const float4*)&As2[kk][tm*16+8];
            a3.v = *(const float4*)&As2[kk][tm*16+12];
            u64 bd[4] = { b0.d[0], b0.d[1], b1.d[0], b1.d[1] };
            u64 ad[8] = { a0.d[0], a0.d[1], a1.d[0], a1.d[1],
                          a2.d[0], a2.d[1], a3.d[0], a3.d[1] };
            #pragma unroll
            for (int i=0;i<8;i++)
                #pragma unroll
                for (int j=0;j<4;j++)
                    acc[i][j] = ffma2(ad[i], bd[j], acc[i][j]);
        }
        __syncthreads();
    }
    #pragma unroll
    for (int i=0;i<8;i++){
        int gr = row0 + tm*8 + i;
        if (gr >= M) continue;
        #pragma unroll
        for (int j=0;j<4;j++){
            float2 v = unpack2(acc[i][j]);
            int gn = col0 + tn*8 + j*2;
            if (gn < N){
                float x = v.x + (bias ? bias[gn] : 0.f);
                if (act) x = tanh_(x);
                C[(size_t)gr*N + gn] = x;
            }
            if (gn+1 < N){
                float y = v.y + (bias ? bias[gn+1] : 0.f);
                if (act) y = tanh_(y);
                C[(size_t)gr*N + gn+1] = y;
            }
        }
    }
}

// ------------- LSTM scan -------------
#define HS 20
#define SCAN_SMEM ((64*G4 + 128*HS)*4)

__global__ __launch_bounds__(256,1)
void scan_kernel(const float* __restrict__ xwFp, const float* __restrict__ xwBp,
                 const float* __restrict__ wTF, const float* __restrict__ wTB,
                 float* __restrict__ hout)
{
    extern __shared__ float sm[];
    float* Ws = sm;
    float* hs = sm + 64*G4;
    int tid = threadIdx.x;
    int dir = blockIdx.x >> 6;
    int grp = blockIdx.x & 63;
    int b0 = grp*8;
    const float* xw = dir ? xwBp : xwFp;
    const float* wD = dir ? wTB : wTF;
    int hOff = dir*128;
    int h  = tid & 127;
    int rg = tid >> 7;

    for (int i=tid;i<64*G4;i+=256) Ws[i] = wD[i];
    for (int i=tid;i<128*HS;i+=256) hs[i] = 0.f;
    float cst[4] = {0.f,0.f,0.f,0.f};
    __syncthreads();

    for (int s=0;s<Tt;s++){
        int t = dir ? (Tt-1-s) : s;
        F4 xv[4];
        #pragma unroll
        for (int r=0;r<4;r++)
            xv[r].v = *(const float4*)&xw[((size_t)(b0+4*rg+r)*Tt + t)*G4 + 4*h];

        u64 aIF[4] = {0,0,0,0}, aGO[4] = {0,0,0,0};
        #pragma unroll 8
        for (int k=0;k<64;k++){
            F4 w;  w.v  = *(const float4*)&Ws[k*G4 + 4*h];
            F4 p0; p0.v = *(const float4*)&hs[k*HS + 8*rg];
            F4 p1; p1.v = *(const float4*)&hs[k*HS + 8*rg + 4];
            aIF[0]=ffma2(p0.d[0], w.d[0], aIF[0]); aGO[0]=ffma2(p0.d[0], w.d[1], aGO[0]);
            aIF[1]=ffma2(p0.d[1], w.d[0], aIF[1]); aGO[1]=ffma2(p0.d[1], w.d[1], aGO[1]);
            aIF[2]=ffma2(p1.d[0], w.d[0], aIF[2]); aGO[2]=ffma2(p1.d[0], w.d[1], aGO[2]);
            aIF[3]=ffma2(p1.d[1], w.d[0], aIF[3]); aGO[3]=ffma2(p1.d[1], w.d[1], aGO[3]);
        }
        for (int kb=64;kb<128;kb+=8){
            F4 w[8];
            #pragma unroll
            for (int j=0;j<8;j++) w[j].v = *(const float4*)&wD[(size_t)(kb+j)*G4 + 4*h];
            #pragma unroll
            for (int j=0;j<8;j++){
                int k = kb+j;
                F4 p0; p0.v = *(const float4*)&hs[k*HS + 8*rg];
                F4 p1; p1.v = *(const float4*)&hs[k*HS + 8*rg + 4];
                aIF[0]=ffma2(p0.d[0], w[j].d[0], aIF[0]); aGO[0]=ffma2(p0.d[0], w[j].d[1], aGO[0]);
                aIF[1]=ffma2(p0.d[1], w[j].d[0], aIF[1]); aGO[1]=ffma2(p0.d[1], w[j].d[1], aGO[1]);
                aIF[2]=ffma2(p1.d[0], w[j].d[0], aIF[2]); aGO[2]=ffma2(p1.d[0], w[j].d[1], aGO[2]);
                aIF[3]=ffma2(p1.d[1], w[j].d[0], aIF[3]); aGO[3]=ffma2(p1.d[1], w[j].d[1], aGO[3]);
            }
        }
        __syncthreads();
        float hnew[4];
        #pragma unroll
        for (int r=0;r<4;r++){
            float2 v1 = unpack2(aIF[r]);
            float2 v2 = unpack2(aGO[r]);
            float gi = v1.x + xv[r].f[0];
            float gf = v1.y + xv[r].f[1];
            float gg = v2.x + xv[r].f[2];
            float go = v2.y + xv[r].f[3];
            float cc = sigf(gf)*cst[r] + sigf(gi)*tanh_(gg);
            cst[r] = cc;
            hnew[r] = sigf(go)*tanh_(cc);
        }
        #pragma unroll
        for (int r=0;r<4;r++){
            *(float2*)&hs[h*HS + 2*(4*rg+r)] = make_float2(hnew[r], hnew[r]);
            hout[((size_t)(b0+4*rg+r)*Tt + t)*256 + hOff + h] = hnew[r];
        }
        __syncthreads();
    }
}

// ------------- attention -------------
__global__ __launch_bounds__(256,1)
void att_kernel(const float* __restrict__ u, const float* __restrict__ h1,
                const float* __restrict__ v, float* __restrict__ att)
{
    __shared__ float sa[Tt];
    __shared__ float red[256];
    int b = blockIdx.x, tid = threadIdx.x;
    for (int t = tid; t < Tt; t += 256){
        const float* ur = u + ((size_t)b*Tt + t)*256;
        float s = 0.f;
        #pragma unroll 8
        for (int k=0;k<256;k++) s += ur[k]*v[k];
        sa[t] = s;
    }
    __syncthreads();
    float m = -3.4e38f;
    for (int t=tid;t<Tt;t+=256) m = fmaxf(m, sa[t]);
    red[tid] = m; __syncthreads();
    for (int off=128; off>0; off>>=1){ if (tid<off) red[tid]=fmaxf(red[tid],red[tid+off]); __syncthreads(); }
    float mx = red[0]; __syncthreads();
    float sum = 0.f;
    for (int t=tid;t<Tt;t+=256){ float e = __expf(sa[t]-mx); sa[t]=e; sum+=e; }
    red[tid] = sum; __syncthreads();
    for (int off=128; off>0; off>>=1){ if (tid<off) red[tid]+=red[tid+off]; __syncthreads(); }
    float inv = __fdividef(1.f, red[0]);
    __syncthreads();
    float acc = 0.f;
    const float* hb = h1 + (size_t)b*Tt*256 + tid;
    #pragma unroll 4
    for (int t=0;t<Tt;t++) acc += hb[(size_t)t*256] * sa[t];
    att[b*256 + tid] = acc * inv;
}

// ------------- launch -------------
extern "C" void kernel_launch(void* const* d_in, const int* in_sizes, int n_in,
                              void* d_out, int out_size)
{
    const float* X      = (const float*)d_in[0];
    const float* wih0f  = (const float*)d_in[1];
    const float* whh0f  = (const float*)d_in[2];
    const float* bih0f  = (const float*)d_in[3];
    const float* bhh0f  = (const float*)d_in[4];
    const float* wih0b  = (const float*)d_in[5];
    const float* whh0b  = (const float*)d_in[6];
    const float* bih0b  = (const float*)d_in[7];
    const float* bhh0b  = (const float*)d_in[8];
    const float* wih1f  = (const float*)d_in[9];
    const float* whh1f  = (const float*)d_in[10];
    const float* bih1f  = (const float*)d_in[11];
    const float* bhh1f  = (const float*)d_in[12];
    const float* wih1b  = (const float*)d_in[13];
    const float* whh1b  = (const float*)d_in[14];
    const float* bih1b  = (const float*)d_in[15];
    const float* bhh1b  = (const float*)d_in[16];
    const float* attW   = (const float*)d_in[17];
    const float* attV   = (const float*)d_in[18];
    const float* headW  = (const float*)d_in[19];
    const float* headB  = (const float*)d_in[20];
    float* out = (float*)d_out;

    cudaFuncSetAttribute(scan_kernel, cudaFuncAttributeMaxDynamicSharedMemorySize, SCAN_SMEM);

    float *xT, *xwF, *xwB, *h0, *h1, *wT, *wi0, *wi1, *bsum, *att;
    __nv_bfloat16 *ahi, *alo, *whi, *wlo;
    cudaGetSymbolAddress((void**)&xT,  g_xT);
    cudaGetSymbolAddress((void**)&xwF, g_xwF);
    cudaGetSymbolAddress((void**)&xwB, g_xwB);
    cudaGetSymbolAddress((void**)&h0,  g_h0);
    cudaGetSymbolAddress((void**)&h1,  g_h1);
    cudaGetSymbolAddress((void**)&wT,  g_wT);
    cudaGetSymbolAddress((void**)&wi0, g_wih0);
    cudaGetSymbolAddress((void**)&wi1, g_wih1);
    cudaGetSymbolAddress((void**)&bsum,g_bsum);
    cudaGetSymbolAddress((void**)&att, g_att);
    cudaGetSymbolAddress((void**)&ahi, g_ahi);
    cudaGetSymbolAddress((void**)&alo, g_alo);
    cudaGetSymbolAddress((void**)&whi, g_whi);
    cudaGetSymbolAddress((void**)&wlo, g_wlo);

    // prep: reorder weights into gate-interleaved layouts, fold biases
    reorder_wih<<<(G4*Cc+255)/256, 256>>>(wih0f, wi0,            Cc);
    reorder_wih<<<(G4*Cc+255)/256, 256>>>(wih0b, wi0 + G4*Cc,    Cc);
    reorder_wih<<<(G4*256+255)/256,256>>>(wih1f, wi1,            256);
    reorder_wih<<<(G4*256+255)/256,256>>>(wih1b, wi1 + G4*256,   256);
    reorder_whh<<<(Hh*G4+255)/256, 256>>>(whh0f, wT + 0*Hh*G4);
    reorder_whh<<<(Hh*G4+255)/256, 256>>>(whh0b, wT + 1*Hh*G4);
    reorder_whh<<<(Hh*G4+255)/256, 256>>>(whh1f, wT + 2*Hh*G4);
    reorder_whh<<<(Hh*G4+255)/256, 256>>>(whh1b, wT + 3*Hh*G4);
    fold_b<<<2,256>>>(bih0f, bhh0f, bsum + 0*G4);
    fold_b<<<2,256>>>(bih0b, bhh0b, bsum + 1*G4);
    fold_b<<<2,256>>>(bih1f, bhh1f, bsum + 2*G4);
    fold_b<<<2,256>>>(bih1b, bhh1b, bsum + 3*G4);

    // weight bf16 splits
    conv_split<<<(512*KP0+255)/256,256>>>(wi0,          whi+WOFF0F, wlo+WOFF0F, 512*KP0, Cc, KP0);
    conv_split<<<(512*KP0+255)/256,256>>>(wi0 + G4*Cc,  whi+WOFF0B, wlo+WOFF0B, 512*KP0, Cc, KP0);
    conv_split<<<(512*256+255)/256,256>>>(wi1,          whi+WOFF1F, wlo+WOFF1F, 512*256, 256, 256);
    conv_split<<<(512*256+255)/256,256>>>(wi1 + G4*256, whi+WOFF1B, wlo+WOFF1B, 512*256, 256, 256);
    conv_splitT<<<(256*256+255)/256,256>>>(attW, whi+WOFFATT, wlo+WOFFATT, 256, 256, 256);

    transposeX<<<dim3((Tt+31)/32,(Cc+31)/32,Bsz), dim3(32,8)>>>(X, xT);

    // layer 0: split x, two tensor GEMMs, scan
    {
        size_t tot = (size_t)BT*KP0;
        conv_split<<<(unsigned)((tot+255)/256),256>>>(xT, ahi, alo, tot, Cc, KP0);
    }
    dim3 g0(4, BT/128);
    mma_gemm<<<g0,256>>>(ahi, alo, whi+WOFF0F, wlo+WOFF0F, bsum + 0*G4, xwF, BT, G4, KP0, 0);
    mma_gemm<<<g0,256>>>(ahi, alo, whi+WOFF0B, wlo+WOFF0B, bsum + 1*G4, xwB, BT, G4, KP0, 0);
    scan_kernel<<<128,256,SCAN_SMEM>>>(xwF, xwB, wT + 0*Hh*G4, wT + 1*Hh*G4, h0);

    // layer 1
    {
        size_t tot = (size_t)BT*256;
        conv_split<<<(unsigned)((tot+255)/256),256>>>(h0, ahi, alo, tot, 256, 256);
    }
    mma_gemm<<<g0,256>>>(ahi, alo, whi+WOFF1F, wlo+WOFF1F, bsum + 2*G4, xwF, BT, G4, 256, 0);
    mma_gemm<<<g0,256>>>(ahi, alo, whi+WOFF1B, wlo+WOFF1B, bsum + 3*G4, xwB, BT, G4, 256, 0);
    scan_kernel<<<128,256,SCAN_SMEM>>>(xwF, xwB, wT + 2*Hh*G4, wT + 3*Hh*G4, h1);

    // attention u = tanh(h1 @ att_W)
    {
        size_t tot = (size_t)BT*256;
        conv_split<<<(unsigned)((tot+255)/256),256>>>(h1, ahi, alo, tot, 256, 256);
    }
    mma_gemm<<<dim3(2, BT/128),256>>>(ahi, alo, whi+WOFFATT, wlo+WOFFATT, (const float*)0, xwF, BT, 256, 256, 1);
    att_kernel<<<Bsz,256>>>(xwF, h1, attV, att);
    // head (fp32)
    gemm128<<<dim3((NCLS+127)/128,(Bsz+127)/128),256>>>(att, headW, headB, out, Bsz, NCLS, 256, 1, 0);
}